// round 16
// baseline (speedup 1.0000x reference)
#include <cuda_runtime.h>
#include <math.h>

// Problem constants
#define BATCH 8
#define FEAT  64
#define HW    262144             // 512*512
#define NSEG  33                 // ids 0..32 (0 = background)
#define NI    32

// Segment-max config (R2/R7-proven loop — body protected in __noinline__ fn)
#define THREADS1 512             // 16 warps = 16 features per (b,fg) group
#define TILEPX   2048            // pixels per work unit
#define NTILE    (HW / TILEPX)   // 128
#define NU       (BATCH * 4 * NTILE)  // 4096 work units
#define NB       456             // 152 SMs * 3 CTAs, exact single wave

#define VEC_ELEMS (BATCH * NI * FEAT)   // 16384

// Per-(b,instance,feature) maxima as float bit patterns (nonneg -> int order ok).
// Statically zeroed; the fused tail re-zeroes after consuming, so every call
// sees identical initial state.
__device__ int g_scratch[VEC_ELEMS];
__device__ unsigned int g_count;   // zero-init; tail resets to 0

extern __shared__ char smem_raw[];

// ---------------------------------------------------------------------------
// Segment-max body: R15's hot loop, isolated as a __noinline__ ABI function
// so ptxas schedules/allocates it independently of the MLP tail code.
// ---------------------------------------------------------------------------
__device__ __noinline__ void segmax_body(const float* __restrict__ enc,
                                         const int*   __restrict__ masks) {
    float* s_acc = (float*)smem_raw;                          // 33*512 floats = 67584 B
    int*   s_ids = (int*)(smem_raw + NSEG * THREADS1 * 4);    // 2048 ints   =  8192 B

    const int tid  = threadIdx.x;
    const int lane = tid & 31;
    const int w    = tid >> 5;
    const int k    = blockIdx.x;

    const int s = (k * NU) / NB;
    const int e = ((k + 1) * NU) / NB;

    int cur = -1;
    int b = 0, f = 0;

    for (int u = s; u < e; ++u) {
        const int bfg = u >> 7;             // u / NTILE
        if (bfg != cur) {
            if (cur >= 0) {
                // flush: column tid is private to this thread; warp-reduce per id
                #pragma unroll
                for (int id = 1; id < NSEG; ++id) {
                    float v = s_acc[(id << 9) + tid];
                    #pragma unroll
                    for (int off = 16; off; off >>= 1)
                        v = fmaxf(v, __shfl_xor_sync(0xffffffffu, v, off));
                    if (lane == 0 && v > 0.0f)
                        atomicMax(&g_scratch[((b * NI) + (id - 1)) * FEAT + f],
                                  __float_as_int(v));
                }
            }
            #pragma unroll
            for (int r = 0; r < NSEG; ++r) s_acc[(r << 9) + tid] = 0.0f;
            cur = bfg;
            b = bfg >> 2;
            f = ((bfg & 3) << 4) | w;
        }
        const int tile = u & (NTILE - 1);

        // Stage mask ids for this tile (premultiplied by 512 = row stride).
        __syncthreads();   // prior tile's s_ids consumers are done
        {
            const int4 m = ((const int4*)(masks + (size_t)b * HW + tile * TILEPX))[tid];
            ((int4*)s_ids)[tid] = make_int4(m.x << 9, m.y << 9, m.z << 9, m.w << 9);
        }
        __syncthreads();

        const float4* src4 = (const float4*)enc
                           + (size_t)(b * FEAT + f) * (HW / 4)
                           + tile * (TILEPX / 4);
        const int4* id4 = (const int4*)s_ids;

        #pragma unroll 4
        for (int g = 0; g < TILEPX / 4 / 32; ++g) {   // 16 iterations
            const int idx = g * 32 + lane;
            const float4 v = src4[idx];
            const int4  o = id4[idx];
            float a;
            a = s_acc[o.x + tid]; if (v.x > a) s_acc[o.x + tid] = v.x;
            a = s_acc[o.y + tid]; if (v.y > a) s_acc[o.y + tid] = v.y;
            a = s_acc[o.z + tid]; if (v.z > a) s_acc[o.z + tid] = v.z;
            a = s_acc[o.w + tid]; if (v.w > a) s_acc[o.w + tid] = v.w;
        }
    }

    // final flush
    #pragma unroll
    for (int id = 1; id < NSEG; ++id) {
        float v = s_acc[(id << 9) + tid];
        #pragma unroll
        for (int off = 16; off; off >>= 1)
            v = fmaxf(v, __shfl_xor_sync(0xffffffffu, v, off));
        if (lane == 0 && v > 0.0f)
            atomicMax(&g_scratch[((b * NI) + (id - 1)) * FEAT + f],
                      __float_as_int(v));
    }
}

// ---------------------------------------------------------------------------
// Fused kernel: protected segmax body + last-block collapsed MLP tail:
//   out[b,c,j,i] = sigmoid( v_i.(W1a W2) + v_j.(W1b W2) + (b1 W2 + b2) )
// ---------------------------------------------------------------------------
__global__ __launch_bounds__(THREADS1, 3)
void fused_kernel(const float* __restrict__ enc,
                  const int*   __restrict__ masks,
                  const float* __restrict__ w1,
                  const float* __restrict__ b1,
                  const float* __restrict__ w2,
                  const float* __restrict__ b2,
                  float*       __restrict__ out_vec,
                  float*       __restrict__ out_conn) {
    segmax_body(enc, masks);

    const int tid = threadIdx.x;

    // ---- last-block-out runs the collapsed MLP ----
    __threadfence();
    __shared__ unsigned int s_rank;
    if (tid == 0) s_rank = atomicAdd(&g_count, 1u);
    __syncthreads();
    if (s_rank != NB - 1) return;
    __threadfence();   // acquire: all blocks' atomicMax results now visible

    // reuse dynamic smem (tail needs ~38 KB < 75776 B)
    float* s_w1 = (float*)smem_raw;        // 4096
    float* s_w2 = s_w1 + 4096;             // 128
    float* s_b1 = s_w2 + 128;              // 32
    float* s_b2 = s_b1 + 32;               // 4
    float* s_m1 = s_b2 + 4;                // 256: (W1a W2)[k][c]
    float* s_m2 = s_m1 + 256;              // 256: (W1b W2)[k][c]
    float* s_c0 = s_m2 + 256;              // 4
    float* s_v  = s_c0 + 4;                // 2 * 32*65 (padded)
    float* s_P  = s_v + 2 * 2080;          // 2 * 128
    float* s_Q  = s_P + 256;               // 2 * 128

    // stage weights (coalesced float4)
    ((float4*)s_w1)[tid]       = ((const float4*)w1)[tid];
    ((float4*)s_w1)[tid + 512] = ((const float4*)w1)[tid + 512];
    if (tid < 32) ((float4*)s_w2)[tid] = ((const float4*)w2)[tid];
    if (tid < 8)  ((float4*)s_b1)[tid] = ((const float4*)b1)[tid];
    if (tid < 4)  s_b2[tid] = b2[tid];
    __syncthreads();

    // fold: m1[k][c] = sum_m w1[k][m] w2[m][c]; m2 likewise for w1[64+k]
    if (tid < 256) {
        const int kk = tid >> 2, c = tid & 3;
        float a1 = 0.0f, a2 = 0.0f;
        #pragma unroll 8
        for (int m = 0; m < 32; ++m) {
            const float w2v = s_w2[m * 4 + c];
            a1 += s_w1[kk * 32 + m] * w2v;
            a2 += s_w1[(64 + kk) * 32 + m] * w2v;
        }
        s_m1[tid] = a1;
        s_m2[tid] = a2;
    } else if (tid < 260) {
        const int c = tid - 256;
        float a = s_b2[c];
        #pragma unroll 8
        for (int m = 0; m < 32; ++m) a += s_b1[m] * s_w2[m * 4 + c];
        s_c0[c] = a;
    }
    __syncthreads();

    // two batches per round
    for (int bb = 0; bb < BATCH; bb += 2) {
        for (int t = tid; t < 2 * NI * FEAT; t += THREADS1) {
            const int bloc = t >> 11;
            const int loc  = t & 2047;
            const int gidx = (bb + bloc) * NI * FEAT + loc;
            const float vv = __int_as_float(g_scratch[gidx]);
            s_v[bloc * 2080 + (loc >> 6) * 65 + (loc & 63)] = vv;
            out_vec[gidx]   = vv;
            g_scratch[gidx] = 0;
        }
        __syncthreads();

        {   // P[i][c] = v_i . m1_c ; Q[j][c] = v_j . m2_c   (512 threads exactly)
            const int bloc = tid >> 8;
            const int t2   = tid & 255;
            const int isQ  = t2 >> 7;
            const int idx  = t2 & 127;
            const int r = idx >> 2, c = idx & 3;
            const float* vm = s_v + bloc * 2080 + r * 65;
            const float* mm = isQ ? s_m2 : s_m1;
            float a = 0.0f;
            #pragma unroll 8
            for (int kk = 0; kk < FEAT; ++kk) a += vm[kk] * mm[kk * 4 + c];
            if (isQ) s_Q[bloc * 128 + idx] = a;
            else     s_P[bloc * 128 + idx] = a;
        }
        __syncthreads();

        #pragma unroll
        for (int rr = 0; rr < 16; ++rr) {
            const int o     = rr * THREADS1 + tid;   // 0..8191
            const int bloc  = o >> 12;
            const int oo    = o & 4095;              // c*1024 + j*32 + i
            const int c  = oo >> 10;
            const int j  = (oo >> 5) & 31;
            const int i  = oo & 31;
            const float t = s_P[bloc * 128 + i * 4 + c]
                          + s_Q[bloc * 128 + j * 4 + c] + s_c0[c];
            out_conn[(size_t)(bb + bloc) * 4096 + oo] = 1.0f / (1.0f + __expf(-t));
        }
        __syncthreads();
    }

    if (tid == 0) g_count = 0;   // restore state for next identical call
}

// ---------------------------------------------------------------------------
// Launch: single fused kernel, single graph node.
// ---------------------------------------------------------------------------
extern "C" void kernel_launch(void* const* d_in, const int* in_sizes, int n_in,
                              void* d_out, int out_size) {
    const float* enc   = (const float*)d_in[0];
    const int*   masks = (const int*)d_in[1];
    const float* w1    = (const float*)d_in[2];
    const float* b1    = (const float*)d_in[3];
    const float* w2    = (const float*)d_in[4];
    const float* b2    = (const float*)d_in[5];

    float* out_vec  = (float*)d_out;
    float* out_conn = out_vec + VEC_ELEMS;

    static bool attr_set = false;
    const int smem_bytes = NSEG * THREADS1 * 4 + TILEPX * 4;  // 75776
    if (!attr_set) {
        cudaFuncSetAttribute(fused_kernel,
                             cudaFuncAttributeMaxDynamicSharedMemorySize, smem_bytes);
        attr_set = true;
    }

    fused_kernel<<<NB, THREADS1, smem_bytes>>>(enc, masks, w1, b1, w2, b2,
                                               out_vec, out_conn);
}

// round 17
// speedup vs baseline: 1.1295x; 1.1295x over previous
#include <cuda_runtime.h>
#include <math.h>

// Problem constants
#define BATCH 8
#define FEAT  64
#define HW    262144             // 512*512
#define NSEG  33                 // ids 0..32 (0 = background)
#define NI    32

// Segment-max config (R2/R7-proven loop, byte-identical body)
#define THREADS1 512             // 16 warps = 16 features per (b,fg) group
#define TILEPX   2048            // pixels per work unit
#define NTILE    (HW / TILEPX)   // 128
#define NU       (BATCH * 4 * NTILE)  // 4096 work units
#define NB       456             // 152 SMs * 3 CTAs: EXACTLY one resident wave

#define VEC_ELEMS (BATCH * NI * FEAT)   // 16384

#define SLICES 57                // blocks per batch in the tail (8*57 = 456)
#define OSLICE 72                // ceil(4096 / 57)

// Per-(b,instance,feature) maxima as float bit patterns (nonneg -> int order ok).
// Statically zeroed; tail re-zeroes after consuming -> identical state per call.
__device__ int g_scratch[VEC_ELEMS];
__device__ unsigned int g_bar;          // grid barrier arrivals (reset each call)
__device__ unsigned int g_bar2;         // post-barrier arrivals (reset each call)
__device__ unsigned int g_cnt[BATCH];   // per-batch tail tickets (reset each call)

extern __shared__ char smem_raw[];

// ---------------------------------------------------------------------------
// Fused kernel: segmax (proven loop) + grid barrier + FULL-GRID MLP tail.
// All 456 blocks are co-resident (one exact wave), so the spin barrier is
// deadlock-free. The tail runs at grid-456 effective -> no low-grid throttle.
//   out[b,c,j,i] = sigmoid( v_i.(W1a W2) + v_j.(W1b W2) + (b1 W2 + b2) )
// ---------------------------------------------------------------------------
__global__ __launch_bounds__(THREADS1, 3)
void fused_kernel(const float* __restrict__ enc,
                  const int*   __restrict__ masks,
                  const float* __restrict__ w1,
                  const float* __restrict__ b1,
                  const float* __restrict__ w2,
                  const float* __restrict__ b2,
                  float*       __restrict__ out_vec,
                  float*       __restrict__ out_conn) {
    float* s_acc = (float*)smem_raw;                          // 33*512 floats = 67584 B
    int*   s_ids = (int*)(smem_raw + NSEG * THREADS1 * 4);    // 2048 ints   =  8192 B

    const int tid  = threadIdx.x;
    const int lane = tid & 31;
    const int w    = tid >> 5;
    const int k    = blockIdx.x;

    const int s = (k * NU) / NB;
    const int e = ((k + 1) * NU) / NB;

    int cur = -1;
    int b = 0, f = 0;

    for (int u = s; u < e; ++u) {
        const int bfg = u >> 7;             // u / NTILE
        if (bfg != cur) {
            if (cur >= 0) {
                // flush: column tid is private to this thread; warp-reduce per id
                #pragma unroll
                for (int id = 1; id < NSEG; ++id) {
                    float v = s_acc[(id << 9) + tid];
                    #pragma unroll
                    for (int off = 16; off; off >>= 1)
                        v = fmaxf(v, __shfl_xor_sync(0xffffffffu, v, off));
                    if (lane == 0 && v > 0.0f)
                        atomicMax(&g_scratch[((b * NI) + (id - 1)) * FEAT + f],
                                  __float_as_int(v));
                }
            }
            #pragma unroll
            for (int r = 0; r < NSEG; ++r) s_acc[(r << 9) + tid] = 0.0f;
            cur = bfg;
            b = bfg >> 2;
            f = ((bfg & 3) << 4) | w;
        }
        const int tile = u & (NTILE - 1);

        // Stage mask ids for this tile (premultiplied by 512 = row stride).
        __syncthreads();   // prior tile's s_ids consumers are done
        {
            const int4 m = ((const int4*)(masks + (size_t)b * HW + tile * TILEPX))[tid];
            ((int4*)s_ids)[tid] = make_int4(m.x << 9, m.y << 9, m.z << 9, m.w << 9);
        }
        __syncthreads();

        const float4* src4 = (const float4*)enc
                           + (size_t)(b * FEAT + f) * (HW / 4)
                           + tile * (TILEPX / 4);
        const int4* id4 = (const int4*)s_ids;

        #pragma unroll 4
        for (int g = 0; g < TILEPX / 4 / 32; ++g) {   // 16 iterations
            const int idx = g * 32 + lane;
            const float4 v = src4[idx];
            const int4  o = id4[idx];
            float a;
            a = s_acc[o.x + tid]; if (v.x > a) s_acc[o.x + tid] = v.x;
            a = s_acc[o.y + tid]; if (v.y > a) s_acc[o.y + tid] = v.y;
            a = s_acc[o.z + tid]; if (v.z > a) s_acc[o.z + tid] = v.z;
            a = s_acc[o.w + tid]; if (v.w > a) s_acc[o.w + tid] = v.w;
        }
    }

    // final flush
    #pragma unroll
    for (int id = 1; id < NSEG; ++id) {
        float v = s_acc[(id << 9) + tid];
        #pragma unroll
        for (int off = 16; off; off >>= 1)
            v = fmaxf(v, __shfl_xor_sync(0xffffffffu, v, off));
        if (lane == 0 && v > 0.0f)
            atomicMax(&g_scratch[((b * NI) + (id - 1)) * FEAT + f],
                      __float_as_int(v));
    }

    // ------------------- grid barrier (all blocks co-resident) -------------
    __threadfence();                       // release this block's scratch writes
    if (tid == 0) {
        atomicAdd(&g_bar, 1u);
        while (*(volatile unsigned int*)&g_bar < NB) __nanosleep(64);
    }
    __syncthreads();
    __threadfence();                       // acquire all blocks' scratch writes

    // barrier-reset bookkeeping: a block increments g_bar2 only AFTER exiting
    // the spin, so the NB-th arriver knows every block has passed -> safe to
    // reset g_bar for the next graph replay.
    if (tid == 0) {
        const unsigned int r2 = atomicAdd(&g_bar2, 1u);
        if (r2 == NB - 1) { g_bar = 0; g_bar2 = 0; }
    }

    // ------------------- full-grid MLP tail ---------------------------------
    // 57 blocks per batch; each redundantly folds the tiny weights (L2-served)
    // and writes a 72-element slice of out_conn[batch].
    float* s_w1 = (float*)smem_raw;        // 4096
    float* s_w2 = s_w1 + 4096;             // 128
    float* s_b1 = s_w2 + 128;              // 32
    float* s_b2 = s_b1 + 32;               // 4
    float* s_m1 = s_b2 + 4;                // 256: (W1a W2)[k][c]
    float* s_m2 = s_m1 + 256;              // 256: (W1b W2)[k][c]
    float* s_c0 = s_m2 + 256;              // 4
    float* s_v  = s_c0 + 4;                // 32*65 (padded)
    float* s_P  = s_v + 2080;              // 128
    float* s_Q  = s_P + 128;               // 128

    const int bb = k % BATCH;              // this block's batch
    const int sl = k / BATCH;              // slice 0..56

    // stage weights (coalesced float4; L2 hits after the first block)
    ((float4*)s_w1)[tid]       = ((const float4*)w1)[tid];
    ((float4*)s_w1)[tid + 512] = ((const float4*)w1)[tid + 512];
    if (tid < 32) ((float4*)s_w2)[tid] = ((const float4*)w2)[tid];
    if (tid < 8)  ((float4*)s_b1)[tid] = ((const float4*)b1)[tid];
    if (tid < 4)  s_b2[tid] = b2[tid];

    // stage this batch's vectors from scratch
    #pragma unroll
    for (int t = tid; t < NI * FEAT; t += THREADS1)
        s_v[(t >> 6) * 65 + (t & 63)] = __int_as_float(g_scratch[bb * NI * FEAT + t]);
    __syncthreads();

    // fold: m1[k][c] = sum_m w1[k][m] w2[m][c]; m2 likewise for w1[64+k]
    if (tid < 256) {
        const int kk = tid >> 2, c = tid & 3;
        float a1 = 0.0f, a2 = 0.0f;
        #pragma unroll 8
        for (int m = 0; m < 32; ++m) {
            const float w2v = s_w2[m * 4 + c];
            a1 += s_w1[kk * 32 + m] * w2v;
            a2 += s_w1[(64 + kk) * 32 + m] * w2v;
        }
        s_m1[tid] = a1;
        s_m2[tid] = a2;
    } else if (tid < 260) {
        const int c = tid - 256;
        float a = s_b2[c];
        #pragma unroll 8
        for (int m = 0; m < 32; ++m) a += s_b1[m] * s_w2[m * 4 + c];
        s_c0[c] = a;
    }
    __syncthreads();

    // P[i][c] = v_i . m1_c ; Q[j][c] = v_j . m2_c
    if (tid < 256) {
        const int isQ = tid >> 7;
        const int idx = tid & 127;
        const int r = idx >> 2, c = idx & 3;
        const float* vm = s_v + r * 65;
        const float* mm = isQ ? s_m2 : s_m1;
        float a = 0.0f;
        #pragma unroll 8
        for (int kk = 0; kk < FEAT; ++kk) a += vm[kk] * mm[kk * 4 + c];
        if (isQ) s_Q[idx] = a;
        else     s_P[idx] = a;
    }
    __syncthreads();

    // this block's output slice: o in [sl*72, min(4096, sl*72+72))
    {
        const int o = sl * OSLICE + tid;
        if (tid < OSLICE && o < 4096) {      // o = c*1024 + j*32 + i
            const int c = o >> 10;
            const int j = (o >> 5) & 31;
            const int i = o & 31;
            const float t = s_P[i * 4 + c] + s_Q[j * 4 + c] + s_c0[c];
            out_conn[(size_t)bb * 4096 + o] = 1.0f / (1.0f + __expf(-t));
        }
    }

    // per-batch cleanup: the 57th arriver writes out_vec and re-zeroes its
    // batch's scratch slice (all 57 blocks' reads completed before arrival).
    __syncthreads();
    __shared__ unsigned int s_rank;
    if (tid == 0) s_rank = atomicAdd(&g_cnt[bb], 1u);
    __syncthreads();
    if (s_rank == SLICES - 1) {
        #pragma unroll
        for (int t = tid; t < NI * FEAT; t += THREADS1) {
            const int gidx = bb * NI * FEAT + t;
            out_vec[gidx]   = s_v[(t >> 6) * 65 + (t & 63)];
            g_scratch[gidx] = 0;
        }
        if (tid == 0) g_cnt[bb] = 0;
    }
}

// ---------------------------------------------------------------------------
// Launch: single fused kernel, single graph node.
// ---------------------------------------------------------------------------
extern "C" void kernel_launch(void* const* d_in, const int* in_sizes, int n_in,
                              void* d_out, int out_size) {
    const float* enc   = (const float*)d_in[0];
    const int*   masks = (const int*)d_in[1];
    const float* w1    = (const float*)d_in[2];
    const float* b1    = (const float*)d_in[3];
    const float* w2    = (const float*)d_in[4];
    const float* b2    = (const float*)d_in[5];

    float* out_vec  = (float*)d_out;
    float* out_conn = out_vec + VEC_ELEMS;

    static bool attr_set = false;
    const int smem_bytes = NSEG * THREADS1 * 4 + TILEPX * 4;  // 75776
    if (!attr_set) {
        cudaFuncSetAttribute(fused_kernel,
                             cudaFuncAttributeMaxDynamicSharedMemorySize, smem_bytes);
        attr_set = true;
    }

    fused_kernel<<<NB, THREADS1, smem_bytes>>>(enc, masks, w1, b1, w2, b2,
                                               out_vec, out_conn);
}